// round 1
// baseline (speedup 1.0000x reference)
#include <cuda_runtime.h>
#include <cuda_bf16.h>

// LearnablePeakExtractor: smooth_peaks = x * sigmoid(10*(x-thresh)) * sigmoid(10*(x-pooled))
//                         peak_mask    = smooth_peaks >= thresh
// thresh = sigmoid(logit_thresh); pooled = 5-wide sliding max, edge-replicated.
//
// Fusion: sig(a)*sig(b) = 1 / ((1+e^-a)(1+e^-b))  -> 2 EX2 + 1 RCP per element.

#define ROWS 256
#define LEN  131072
#define VPR  (LEN / 4)   // float4 vectors per row = 32768

__global__ __launch_bounds__(256)
void peak_kernel(const float* __restrict__ in,
                 const float* __restrict__ logit_thresh,
                 float* __restrict__ out_smooth,
                 float* __restrict__ out_mask,
                 int write_mask)
{
    const int row = blockIdx.y;
    const int vc  = blockIdx.x * blockDim.x + threadIdx.x;   // vec4 index in row

    const float4* rp = reinterpret_cast<const float4*>(in + (size_t)row * LEN);
    float4 c = rp[vc];

    // neighbors with edge replication
    float lx, ly, rx, ry;
    if (vc > 0)        { float4 p = rp[vc - 1]; lx = p.z; ly = p.w; }
    else               { lx = c.x; ly = c.x; }
    if (vc < VPR - 1)  { float4 n = rp[vc + 1]; rx = n.x; ry = n.y; }
    else               { rx = c.w; ry = c.w; }

    // sliding window max (window=5) for the 4 elements
    float m01  = fmaxf(c.x, c.y);
    float m12  = fmaxf(c.y, c.z);
    float m23  = fmaxf(c.z, c.w);
    float m012 = fmaxf(m01, c.z);
    float m123 = fmaxf(m12, c.w);
    float m0123 = fmaxf(m01, m23);

    float p0 = fmaxf(fmaxf(lx, ly), m012);          // x[-2..2]
    float p1 = fmaxf(ly, m0123);                    // x[-1..3]
    float p2 = fmaxf(m0123, rx);                    // x[0..4]
    float p3 = fmaxf(m123, fmaxf(rx, ry));          // x[1..5]

    // threshold (scalar input; broadcast via L1/constant path)
    float tl = logit_thresh[0];
    float thresh = __fdividef(1.0f, 1.0f + __expf(-tl));

    // fused double-sigmoid: smooth = x / ((1+e^{10(thresh-x)})(1+e^{10(pooled-x)}))
    float s0, s1, s2, s3;
    {
        float e1 = __expf(10.0f * (thresh - c.x));
        float e2 = __expf(10.0f * (p0     - c.x));
        s0 = __fdividef(c.x, (1.0f + e1) * (1.0f + e2));
    }
    {
        float e1 = __expf(10.0f * (thresh - c.y));
        float e2 = __expf(10.0f * (p1     - c.y));
        s1 = __fdividef(c.y, (1.0f + e1) * (1.0f + e2));
    }
    {
        float e1 = __expf(10.0f * (thresh - c.z));
        float e2 = __expf(10.0f * (p2     - c.z));
        s2 = __fdividef(c.z, (1.0f + e1) * (1.0f + e2));
    }
    {
        float e1 = __expf(10.0f * (thresh - c.w));
        float e2 = __expf(10.0f * (p3     - c.w));
        s3 = __fdividef(c.w, (1.0f + e1) * (1.0f + e2));
    }

    const size_t voff = (size_t)row * VPR + vc;
    reinterpret_cast<float4*>(out_smooth)[voff] = make_float4(s0, s1, s2, s3);

    if (write_mask) {
        float4 m = make_float4(s0 >= thresh ? 1.0f : 0.0f,
                               s1 >= thresh ? 1.0f : 0.0f,
                               s2 >= thresh ? 1.0f : 0.0f,
                               s3 >= thresh ? 1.0f : 0.0f);
        reinterpret_cast<float4*>(out_mask)[voff] = m;
    }
}

extern "C" void kernel_launch(void* const* d_in, const int* in_sizes, int n_in,
                              void* d_out, int out_size)
{
    const float* peak_map     = (const float*)d_in[0];
    const float* logit_thresh = (const float*)d_in[1];
    float* out = (float*)d_out;

    const long long N = (long long)ROWS * LEN;   // 33,554,432
    int write_mask = (out_size >= 2 * N) ? 1 : 0;

    dim3 grid(VPR / 256, ROWS);   // (128, 256)
    peak_kernel<<<grid, 256>>>(peak_map, logit_thresh,
                               out, out + N, write_mask);
}